// round 4
// baseline (speedup 1.0000x reference)
#include <cuda_runtime.h>
#include <cuda_bf16.h>
#include <cstdint>
#include <cfloat>

// ─── shapes ───────────────────────────────────────────────────────────────
#define BATCH   2
#define NBAND   40
#define BB      (BATCH * NBAND)
#define NC      64
#define NT      1500
#define TP      1536          // padded time
#define NCODE   1024
#define KEXT    192           // [xh|xh|xl] · [ch|cl|ch]
#define TT      128           // t rows per CTA (GEMM M)
#define NCH     128           // codes per chunk (GEMM N)
#define NCHUNK  (NCODE / NCH) // 8
#define MARGIN  2e-3f

// smem layout (bytes): A[128][400] | B0[128][400] | B1[128][400] | ns[1024]f32
// epilogue reuse: gs = B0 region (128*65*4 = 33280 B), sidx after it (512 B)
#define ROWB    400
#define SM_A    0
#define SM_B    51200
#define BBUF    51200
#define SM_NS   153600
#define SM_GS   SM_B
#define SM_IDX  (SM_B + 33280)
#define SM_TOT  157696

// ─── device scratch (no allocs allowed) ───────────────────────────────────
__device__ __align__(16) __nv_bfloat16 g_xext[BB * TP * KEXT];
__device__ __align__(16) __nv_bfloat16 g_cbext[NBAND * NCODE * KEXT];
__device__ float g_cnorm[NBAND * NCODE];
__device__ int   g_idx[BB * TP];
__device__ float g_gap[BB * TP];

// ─── PTX helpers (portable sm_80+) ─────────────────────────────────────────
__device__ __forceinline__ uint32_t smem_u32(const void* p) {
    uint32_t a;
    asm("{ .reg .u64 t; cvta.to.shared.u64 t, %1; cvt.u32.u64 %0, t; }" : "=r"(a) : "l"(p));
    return a;
}
#define CP_ASYNC16(d, s)  asm volatile("cp.async.cg.shared.global [%0], [%1], 16;" :: "r"(d), "l"(s))
#define CP_COMMIT()       asm volatile("cp.async.commit_group;" ::: "memory")
#define CP_WAIT(n)        asm volatile("cp.async.wait_group %0;" :: "n"(n) : "memory")

__device__ __forceinline__ void ldsm_x4(uint32_t& r0, uint32_t& r1, uint32_t& r2, uint32_t& r3, uint32_t a) {
    asm volatile("ldmatrix.sync.aligned.m8n8.x4.shared.b16 {%0,%1,%2,%3}, [%4];"
                 : "=r"(r0), "=r"(r1), "=r"(r2), "=r"(r3) : "r"(a));
}
__device__ __forceinline__ void mma16816(float* d, uint32_t a0, uint32_t a1, uint32_t a2, uint32_t a3,
                                         uint32_t b0, uint32_t b1) {
    asm volatile("mma.sync.aligned.m16n8k16.row.col.f32.bf16.bf16.f32 "
                 "{%0,%1,%2,%3}, {%4,%5,%6,%7}, {%8,%9}, {%0,%1,%2,%3};"
                 : "+f"(d[0]), "+f"(d[1]), "+f"(d[2]), "+f"(d[3])
                 : "r"(a0), "r"(a1), "r"(a2), "r"(a3), "r"(b0), "r"(b1));
}

// ─── K1: split + transpose x → g_xext[bb][t][ xh | xh | xl ] ──────────────
__global__ __launch_bounds__(256) void k_split_x(const float* __restrict__ x) {
    __shared__ float sm[NC * TT];
    int bb = blockIdx.y, t0 = blockIdx.x * TT;
    for (int i = threadIdx.x; i < NC * TT; i += 256) {
        int c = i >> 7, tl = i & 127, t = t0 + tl;
        sm[i] = (t < NT) ? x[((size_t)bb * NC + c) * NT + t] : 0.f;
    }
    __syncthreads();
    __nv_bfloat16* dst = g_xext + ((size_t)bb * TP + t0) * KEXT;
    for (int i = threadIdx.x; i < TT * KEXT; i += 256) {
        int tl = i / KEXT, kc = i % KEXT, c = kc & 63;
        float v = sm[c * TT + tl];
        __nv_bfloat16 h = __float2bfloat16(v);
        dst[i] = (kc < 128) ? h : __float2bfloat16(v - __bfloat162float(h));
    }
}

// ─── K2: split codebook → g_cbext[band][k][ ch | cl | ch ], + 0.5‖c‖² ─────
__global__ __launch_bounds__(256) void k_split_cb(const float* __restrict__ cb) {
    int row = blockIdx.x * 8 + (threadIdx.x >> 5);
    int lid = threadIdx.x & 31;
    if (row >= NBAND * NCODE) return;
    float v0 = cb[(size_t)row * NC + lid];
    float v1 = cb[(size_t)row * NC + lid + 32];
    float s = v0 * v0 + v1 * v1;
#pragma unroll
    for (int m = 16; m > 0; m >>= 1) s += __shfl_xor_sync(0xFFFFFFFF, s, m);
    if (lid == 0) g_cnorm[row] = 0.5f * s;
    __nv_bfloat16 h0 = __float2bfloat16(v0), h1 = __float2bfloat16(v1);
    __nv_bfloat16 l0 = __float2bfloat16(v0 - __bfloat162float(h0));
    __nv_bfloat16 l1 = __float2bfloat16(v1 - __bfloat162float(h1));
    __nv_bfloat16* d = g_cbext + (size_t)row * KEXT;
    d[lid] = h0;       d[lid + 32] = h1;
    d[lid + 64] = l0;  d[lid + 96] = l1;
    d[lid + 128] = h0; d[lid + 160] = h1;
}

// ─── K3: mma.sync GEMM + top-2 + fused gather/store ───────────────────────
__global__ __launch_bounds__(256, 1) void k_vq_mma(const float* __restrict__ cbf,
                                                   float* __restrict__ out) {
    extern __shared__ char smc[];
    const uint32_t smem = smem_u32(smc);
    const int tid = threadIdx.x, wid = tid >> 5, lid = tid & 31;
    const int bb = blockIdx.y, band = bb % NBAND, t0 = blockIdx.x * TT;

    const char* asrc  = (const char*)(g_xext + ((size_t)bb * TP + t0) * KEXT);
    const char* cbsrc = (const char*)(g_cbext + (size_t)band * NCODE * KEXT);

    for (int i = tid; i < 3072; i += 256) {
        int row = i / 24, seg = i % 24;
        CP_ASYNC16(smem + SM_A + row * ROWB + seg * 16, asrc + row * 384 + seg * 16);
    }
    CP_ASYNC16(smem + SM_NS + tid * 16, (const char*)(g_cnorm + band * NCODE) + tid * 16);
    for (int i = tid; i < 3072; i += 256) {
        int row = i / 24, seg = i % 24;
        CP_ASYNC16(smem + SM_B + row * ROWB + seg * 16, cbsrc + row * 384 + seg * 16);
    }
    CP_COMMIT();

    const uint32_t lm_off = (uint32_t)(lid & 15) * ROWB + ((uint32_t)(lid >> 4) << 4);
    const uint32_t a_addr0 = smem + SM_A + (uint32_t)(wid * 16) * ROWB + lm_off;

    float v1a = -FLT_MAX, v2a = -FLT_MAX, v1b = -FLT_MAX, v2b = -FLT_MAX;
    int   i1a = 0, i1b = 0;
    const int colb = 2 * (lid & 3);

    for (int ch = 0; ch < NCHUNK; ch++) {
        if (ch > 0) __syncthreads();
        if (ch < NCHUNK - 1) {
            const char* src = cbsrc + (size_t)(ch + 1) * NCH * 384;
            uint32_t dst = smem + SM_B + ((ch + 1) & 1) * BBUF;
            for (int i = tid; i < 3072; i += 256) {
                int row = i / 24, seg = i % 24;
                CP_ASYNC16(dst + row * ROWB + seg * 16, src + row * 384 + seg * 16);
            }
            CP_COMMIT();
            CP_WAIT(1);
        } else {
            CP_WAIT(0);
        }
        __syncthreads();

        float acc[16][4];
        const float* nsp = (const float*)(smc + SM_NS) + ch * NCH + colb;
#pragma unroll
        for (int n = 0; n < 16; n++) {
            float2 ns2 = *(const float2*)(nsp + n * 8);
            acc[n][0] = -ns2.x; acc[n][1] = -ns2.y;
            acc[n][2] = -ns2.x; acc[n][3] = -ns2.y;
        }

        const uint32_t b_addr0 = smem + SM_B + (ch & 1) * BBUF + lm_off;
#pragma unroll
        for (int ks = 0; ks < 12; ks++) {
            uint32_t a0, a1, a2, a3;
            ldsm_x4(a0, a1, a2, a3, a_addr0 + ks * 32);
#pragma unroll
            for (int np = 0; np < 8; np++) {
                uint32_t b0, b1, b2, b3;
                ldsm_x4(b0, b1, b2, b3, b_addr0 + (uint32_t)(np * 16) * ROWB + ks * 32);
                mma16816(acc[2 * np],     a0, a1, a2, a3, b0, b2);
                mma16816(acc[2 * np + 1], a0, a1, a2, a3, b1, b3);
            }
        }

#pragma unroll
        for (int n = 0; n < 16; n++) {
            int k0 = ch * NCH + n * 8 + colb;
#pragma unroll
            for (int e = 0; e < 2; e++) {
                float va = acc[n][e], vb = acc[n][2 + e];
                int k = k0 + e;
                if (va > v1a) { v2a = v1a; v1a = va; i1a = k; } else if (va > v2a) v2a = va;
                if (vb > v1b) { v2b = v1b; v1b = vb; i1b = k; } else if (vb > v2b) v2b = vb;
            }
        }
    }

    // quad-lane merge; exact cross-lane ties force gap=0 (→ fixup handles them)
#pragma unroll
    for (int m = 1; m <= 2; m <<= 1) {
        float ov1 = __shfl_xor_sync(0xFFFFFFFF, v1a, m);
        int   oi1 = __shfl_xor_sync(0xFFFFFFFF, i1a, m);
        float ov2 = __shfl_xor_sync(0xFFFFFFFF, v2a, m);
        if (ov1 > v1a || (ov1 == v1a && oi1 < i1a)) { v2a = fmaxf(v1a, ov2); v1a = ov1; i1a = oi1; }
        else v2a = fmaxf(v2a, ov1);
        ov1 = __shfl_xor_sync(0xFFFFFFFF, v1b, m);
        oi1 = __shfl_xor_sync(0xFFFFFFFF, i1b, m);
        ov2 = __shfl_xor_sync(0xFFFFFFFF, v2b, m);
        if (ov1 > v1b || (ov1 == v1b && oi1 < i1b)) { v2b = fmaxf(v1b, ov2); v1b = ov1; i1b = oi1; }
        else v2b = fmaxf(v2b, ov1);
    }
    __syncthreads();   // all chunk-7 compute done; B buffers now reusable
    if ((lid & 3) == 0) {
        int tlA = wid * 16 + (lid >> 2);
        int tA = t0 + tlA;
        g_idx[bb * TP + tA] = i1a;      g_gap[bb * TP + tA] = v1a - v2a;
        g_idx[bb * TP + tA + 8] = i1b;  g_gap[bb * TP + tA + 8] = v1b - v2b;
        *(int*)(smc + SM_IDX + tlA * 4) = i1a;
        *(int*)(smc + SM_IDX + (tlA + 8) * 4) = i1b;
    }
    __syncthreads();

    // fused gather: cb rows → smem (padded 65) → coalesced-along-t store
    float* gs = (float*)(smc + SM_GS);
    const int* sidx = (const int*)(smc + SM_IDX);
    for (int i = tid; i < TT * NC; i += 256) {
        int tl = i >> 6, c = i & 63;
        gs[tl * 65 + c] = cbf[((size_t)band * NCODE + sidx[tl]) * NC + c];
    }
    __syncthreads();
    for (int i = tid; i < NC * TT; i += 256) {
        int c = i >> 7, tl = i & 127, t = t0 + tl;
        if (t < NT) out[((size_t)bb * NC + c) * NT + t] = gs[tl * 65 + c];
    }
}

// ─── K4: ballot-compacted exact fixup (rewrites g_idx AND output rows) ────
#define FIX_BLOCKS 296
__global__ __launch_bounds__(256) void k_fixup(const float* __restrict__ x,
                                               const float* __restrict__ cb,
                                               float* __restrict__ out) {
    const int lid = threadIdx.x & 31;
    const int gwid = blockIdx.x * 8 + (threadIdx.x >> 5);
    const int nwarp = FIX_BLOCKS * 8;
    const int nchunks = (BB * NT + 31) / 32;

    for (int cw = gwid; cw < nchunks; cw += nwarp) {
        int ri = cw * 32 + lid;
        bool flag = false;
        int bb = 0, t = 0;
        if (ri < BB * NT) {
            bb = ri / NT; t = ri - bb * NT;
            flag = (g_gap[bb * TP + t] < MARGIN);
        }
        unsigned mask = __ballot_sync(0xFFFFFFFF, flag);
        while (mask) {
            int src = __ffs(mask) - 1;
            mask &= mask - 1;
            int fbb = __shfl_sync(0xFFFFFFFF, bb, src);
            int ft  = __shfl_sync(0xFFFFFFFF, t, src);
            int band = fbb % NBAND;

            float xr[NC];
#pragma unroll
            for (int c = 0; c < NC; c++) xr[c] = x[((size_t)fbb * NC + c) * NT + ft];

            float bv = -FLT_MAX; int bi = 0;
            for (int k = lid; k < NCODE; k += 32) {
                const float4* row = (const float4*)(cb + ((size_t)band * NCODE + k) * NC);
                float s = 0.f;
#pragma unroll
                for (int q = 0; q < NC / 4; q++) {
                    float4 v = row[q];
                    s += xr[4 * q] * v.x + xr[4 * q + 1] * v.y + xr[4 * q + 2] * v.z + xr[4 * q + 3] * v.w;
                }
                s -= g_cnorm[band * NCODE + k];
                if (s > bv) { bv = s; bi = k; }
            }
#pragma unroll
            for (int m = 16; m > 0; m >>= 1) {
                float ov = __shfl_xor_sync(0xFFFFFFFF, bv, m);
                int   oi = __shfl_xor_sync(0xFFFFFFFF, bi, m);
                if (ov > bv || (ov == bv && oi < bi)) { bv = ov; bi = oi; }
            }
            if (lid == 0) g_idx[fbb * TP + ft] = bi;
            // rewrite this row's 64 output floats
            const float* crow = cb + ((size_t)band * NCODE + bi) * NC;
#pragma unroll
            for (int c = lid; c < NC; c += 32)
                out[((size_t)fbb * NC + c) * NT + ft] = crow[c];
        }
    }
}

// ─── launch ───────────────────────────────────────────────────────────────
extern "C" void kernel_launch(void* const* d_in, const int* in_sizes, int n_in,
                              void* d_out, int out_size) {
    const float* x  = (const float*)d_in[0];
    const float* cb = (const float*)d_in[1];
    float* out = (float*)d_out;

    dim3 tiles(TP / TT, BB);  // (12, 80)
    k_split_x<<<tiles, 256>>>(x);
    k_split_cb<<<(NBAND * NCODE + 7) / 8, 256>>>(cb);

    cudaFuncSetAttribute(k_vq_mma, cudaFuncAttributeMaxDynamicSharedMemorySize, SM_TOT);
    k_vq_mma<<<tiles, 256, SM_TOT>>>(cb, out);

    k_fixup<<<FIX_BLOCKS, 256>>>(x, cb, out);
}

// round 5
// speedup vs baseline: 1.3049x; 1.3049x over previous
#include <cuda_runtime.h>
#include <cuda_bf16.h>
#include <cstdint>
#include <cfloat>

// ─── shapes ───────────────────────────────────────────────────────────────
#define BATCH   2
#define NBAND   40
#define BB      (BATCH * NBAND)
#define NC      64
#define NT      1500
#define TP      1536          // padded time
#define NCODE   1024
#define KEXT    192           // [xh|xh|xl] · [ch|cl|ch]
#define TT      128           // t rows per CTA (GEMM M)
#define NCH     64            // codes per chunk (GEMM N)
#define NCHUNK  (NCODE / NCH) // 16
#define MARGIN  2e-3f

// smem (bytes): A[128][400] | B0[64][400] | B1[64][400] | ns[1024]f32
// epilogue reuse: gs (128*65*4=33280) + sidx at SM_B
#define ROWB    400
#define SM_A    0
#define SM_B    51200
#define BBUF    25600
#define SM_NS   102400
#define SM_GS   SM_B
#define SM_IDX  (SM_B + 33280)
#define SM_TOT  106496

// ─── device scratch ────────────────────────────────────────────────────────
__device__ __align__(16) __nv_bfloat16 g_xext[BB * TP * KEXT];
__device__ __align__(16) __nv_bfloat16 g_cbext[NBAND * NCODE * KEXT];
__device__ float g_cnorm[NBAND * NCODE];
__device__ int   g_fixcnt;
__device__ int   g_fixlist[BB * NT];

// ─── PTX helpers (portable sm_80+) ─────────────────────────────────────────
__device__ __forceinline__ uint32_t smem_u32(const void* p) {
    uint32_t a;
    asm("{ .reg .u64 t; cvta.to.shared.u64 t, %1; cvt.u32.u64 %0, t; }" : "=r"(a) : "l"(p));
    return a;
}
#define CP_ASYNC16(d, s)  asm volatile("cp.async.cg.shared.global [%0], [%1], 16;" :: "r"(d), "l"(s))
#define CP_COMMIT()       asm volatile("cp.async.commit_group;" ::: "memory")
#define CP_WAIT(n)        asm volatile("cp.async.wait_group %0;" :: "n"(n) : "memory")

__device__ __forceinline__ void ldsm_x4(uint32_t& r0, uint32_t& r1, uint32_t& r2, uint32_t& r3, uint32_t a) {
    asm volatile("ldmatrix.sync.aligned.m8n8.x4.shared.b16 {%0,%1,%2,%3}, [%4];"
                 : "=r"(r0), "=r"(r1), "=r"(r2), "=r"(r3) : "r"(a));
}
__device__ __forceinline__ void mma16816(float* d, uint32_t a0, uint32_t a1, uint32_t a2, uint32_t a3,
                                         uint32_t b0, uint32_t b1) {
    asm volatile("mma.sync.aligned.m16n8k16.row.col.f32.bf16.bf16.f32 "
                 "{%0,%1,%2,%3}, {%4,%5,%6,%7}, {%8,%9}, {%0,%1,%2,%3};"
                 : "+f"(d[0]), "+f"(d[1]), "+f"(d[2]), "+f"(d[3])
                 : "r"(a0), "r"(a1), "r"(a2), "r"(a3), "r"(b0), "r"(b1));
}

// ─── K1: split + transpose x → g_xext[bb][t][ xh | xh | xl ] ──────────────
__global__ __launch_bounds__(256) void k_split_x(const float* __restrict__ x) {
    __shared__ float sm[NC * TT];
    if (blockIdx.x == 0 && blockIdx.y == 0 && threadIdx.x == 0) g_fixcnt = 0;
    int bb = blockIdx.y, t0 = blockIdx.x * TT;
    for (int i = threadIdx.x; i < NC * TT; i += 256) {
        int c = i >> 7, tl = i & 127, t = t0 + tl;
        sm[i] = (t < NT) ? x[((size_t)bb * NC + c) * NT + t] : 0.f;
    }
    __syncthreads();
    __nv_bfloat16* dst = g_xext + ((size_t)bb * TP + t0) * KEXT;
    for (int i = threadIdx.x; i < TT * KEXT; i += 256) {
        int tl = i / KEXT, kc = i % KEXT, c = kc & 63;
        float v = sm[c * TT + tl];
        __nv_bfloat16 h = __float2bfloat16(v);
        dst[i] = (kc < 128) ? h : __float2bfloat16(v - __bfloat162float(h));
    }
}

// ─── K2: split codebook → [ ch | cl | ch ], + 0.5‖c‖² ─────────────────────
__global__ __launch_bounds__(256) void k_split_cb(const float* __restrict__ cb) {
    int row = blockIdx.x * 8 + (threadIdx.x >> 5);
    int lid = threadIdx.x & 31;
    if (row >= NBAND * NCODE) return;
    float v0 = cb[(size_t)row * NC + lid];
    float v1 = cb[(size_t)row * NC + lid + 32];
    float s = v0 * v0 + v1 * v1;
#pragma unroll
    for (int m = 16; m > 0; m >>= 1) s += __shfl_xor_sync(0xFFFFFFFF, s, m);
    if (lid == 0) g_cnorm[row] = 0.5f * s;
    __nv_bfloat16 h0 = __float2bfloat16(v0), h1 = __float2bfloat16(v1);
    __nv_bfloat16 l0 = __float2bfloat16(v0 - __bfloat162float(h0));
    __nv_bfloat16 l1 = __float2bfloat16(v1 - __bfloat162float(h1));
    __nv_bfloat16* d = g_cbext + (size_t)row * KEXT;
    d[lid] = h0;       d[lid + 32] = h1;
    d[lid + 64] = l0;  d[lid + 96] = l1;
    d[lid + 128] = h0; d[lid + 160] = h1;
}

// ─── K3: mma.sync GEMM + top-2 + flag-append + fused gather ───────────────
__global__ __launch_bounds__(256, 2) void k_vq_mma(const float* __restrict__ cbf,
                                                   float* __restrict__ out) {
    extern __shared__ char smc[];
    const uint32_t smem = smem_u32(smc);
    const int tid = threadIdx.x, wid = tid >> 5, lid = tid & 31;
    const int bb = blockIdx.y, band = bb % NBAND, t0 = blockIdx.x * TT;

    const char* asrc  = (const char*)(g_xext + ((size_t)bb * TP + t0) * KEXT);
    const char* cbsrc = (const char*)(g_cbext + (size_t)band * NCODE * KEXT);

    // group 0: A tile + ns + B chunk 0
    for (int i = tid; i < 3072; i += 256) {
        int row = i / 24, seg = i % 24;
        CP_ASYNC16(smem + SM_A + row * ROWB + seg * 16, asrc + row * 384 + seg * 16);
    }
    CP_ASYNC16(smem + SM_NS + tid * 16, (const char*)(g_cnorm + band * NCODE) + tid * 16);
    for (int i = tid; i < NCH * 24; i += 256) {
        int row = i / 24, seg = i % 24;
        CP_ASYNC16(smem + SM_B + row * ROWB + seg * 16, cbsrc + row * 384 + seg * 16);
    }
    CP_COMMIT();

    const uint32_t lm_off = (uint32_t)(lid & 15) * ROWB + ((uint32_t)(lid >> 4) << 4);
    const uint32_t a_addr0 = smem + SM_A + (uint32_t)(wid * 16) * ROWB + lm_off;

    float v1a = -FLT_MAX, v2a = -FLT_MAX, v1b = -FLT_MAX, v2b = -FLT_MAX;
    int   i1a = 0, i1b = 0;
    const int colb = 2 * (lid & 3);

    for (int ch = 0; ch < NCHUNK; ch++) {
        if (ch > 0) __syncthreads();
        if (ch < NCHUNK - 1) {
            const char* src = cbsrc + (size_t)(ch + 1) * NCH * 384;
            uint32_t dst = smem + SM_B + ((ch + 1) & 1) * BBUF;
            for (int i = tid; i < NCH * 24; i += 256) {
                int row = i / 24, seg = i % 24;
                CP_ASYNC16(dst + row * ROWB + seg * 16, src + row * 384 + seg * 16);
            }
            CP_COMMIT();
            CP_WAIT(1);
        } else {
            CP_WAIT(0);
        }
        __syncthreads();

        float acc[8][4];
        const float* nsp = (const float*)(smc + SM_NS) + ch * NCH + colb;
#pragma unroll
        for (int n = 0; n < 8; n++) {
            float2 ns2 = *(const float2*)(nsp + n * 8);
            acc[n][0] = -ns2.x; acc[n][1] = -ns2.y;
            acc[n][2] = -ns2.x; acc[n][3] = -ns2.y;
        }

        const uint32_t b_addr0 = smem + SM_B + (ch & 1) * BBUF + lm_off;
#pragma unroll
        for (int ks = 0; ks < 12; ks++) {
            uint32_t a0, a1, a2, a3;
            ldsm_x4(a0, a1, a2, a3, a_addr0 + ks * 32);
#pragma unroll
            for (int np = 0; np < 4; np++) {
                uint32_t b0, b1, b2, b3;
                ldsm_x4(b0, b1, b2, b3, b_addr0 + (uint32_t)(np * 16) * ROWB + ks * 32);
                mma16816(acc[2 * np],     a0, a1, a2, a3, b0, b2);
                mma16816(acc[2 * np + 1], a0, a1, a2, a3, b1, b3);
            }
        }

#pragma unroll
        for (int n = 0; n < 8; n++) {
            int k0 = ch * NCH + n * 8 + colb;
#pragma unroll
            for (int e = 0; e < 2; e++) {
                float va = acc[n][e], vb = acc[n][2 + e];
                int k = k0 + e;
                if (va > v1a) { v2a = v1a; v1a = va; i1a = k; } else if (va > v2a) v2a = va;
                if (vb > v1b) { v2b = v1b; v1b = vb; i1b = k; } else if (vb > v2b) v2b = vb;
            }
        }
    }

    // quad-lane merge; exact cross-lane ties force gap=0 → flagged → fixup
#pragma unroll
    for (int m = 1; m <= 2; m <<= 1) {
        float ov1 = __shfl_xor_sync(0xFFFFFFFF, v1a, m);
        int   oi1 = __shfl_xor_sync(0xFFFFFFFF, i1a, m);
        float ov2 = __shfl_xor_sync(0xFFFFFFFF, v2a, m);
        if (ov1 > v1a || (ov1 == v1a && oi1 < i1a)) { v2a = fmaxf(v1a, ov2); v1a = ov1; i1a = oi1; }
        else v2a = fmaxf(v2a, ov1);
        ov1 = __shfl_xor_sync(0xFFFFFFFF, v1b, m);
        oi1 = __shfl_xor_sync(0xFFFFFFFF, i1b, m);
        ov2 = __shfl_xor_sync(0xFFFFFFFF, v2b, m);
        if (ov1 > v1b || (ov1 == v1b && oi1 < i1b)) { v2b = fmaxf(v1b, ov2); v1b = ov1; i1b = oi1; }
        else v2b = fmaxf(v2b, ov1);
    }
    __syncthreads();   // all MMA/smem reads done; B region reusable
    if ((lid & 3) == 0) {
        int tlA = wid * 16 + (lid >> 2);
        int tA = t0 + tlA;
        *(int*)(smc + SM_IDX + tlA * 4) = i1a;
        *(int*)(smc + SM_IDX + (tlA + 8) * 4) = i1b;
        if (tA < NT && v1a - v2a < MARGIN) {
            int p = atomicAdd(&g_fixcnt, 1);
            g_fixlist[p] = (bb << 11) | tA;
        }
        if (tA + 8 < NT && v1b - v2b < MARGIN) {
            int p = atomicAdd(&g_fixcnt, 1);
            g_fixlist[p] = (bb << 11) | (tA + 8);
        }
    }
    __syncthreads();

    // fused gather: cb rows → smem (padded 65) → coalesced-along-t store
    float* gs = (float*)(smc + SM_GS);
    const int* sidx = (const int*)(smc + SM_IDX);
    for (int i = tid; i < TT * NC; i += 256) {
        int tl = i >> 6, c = i & 63;
        gs[tl * 65 + c] = cbf[((size_t)band * NCODE + sidx[tl]) * NC + c];
    }
    __syncthreads();
    for (int i = tid; i < NC * TT; i += 256) {
        int c = i >> 7, tl = i & 127, t = t0 + tl;
        if (t < NT) out[((size_t)bb * NC + c) * NT + t] = gs[tl * 65 + c];
    }
}

// ─── K4: exact fixup, warp-per-row over compact list (even distribution) ──
#define FIX_BLOCKS 592
__global__ __launch_bounds__(256) void k_fixup(const float* __restrict__ x,
                                               const float* __restrict__ cb,
                                               float* __restrict__ out) {
    const int lid = threadIdx.x & 31;
    const int gwid = blockIdx.x * 8 + (threadIdx.x >> 5);
    const int nwarp = FIX_BLOCKS * 8;
    const int nrows = g_fixcnt;

    for (int r = gwid; r < nrows; r += nwarp) {
        int id = g_fixlist[r];
        int fbb = id >> 11, ft = id & 2047;
        int band = fbb % NBAND;

        float xr[NC];
#pragma unroll
        for (int c = 0; c < NC; c++) xr[c] = x[((size_t)fbb * NC + c) * NT + ft];

        float bv = -FLT_MAX; int bi = 0;
        for (int k = lid; k < NCODE; k += 32) {
            const float4* row = (const float4*)(cb + ((size_t)band * NCODE + k) * NC);
            float s = 0.f;
#pragma unroll
            for (int q = 0; q < NC / 4; q++) {
                float4 v = row[q];
                s += xr[4 * q] * v.x + xr[4 * q + 1] * v.y + xr[4 * q + 2] * v.z + xr[4 * q + 3] * v.w;
            }
            s -= g_cnorm[band * NCODE + k];
            if (s > bv) { bv = s; bi = k; }
        }
#pragma unroll
        for (int m = 16; m > 0; m >>= 1) {
            float ov = __shfl_xor_sync(0xFFFFFFFF, bv, m);
            int   oi = __shfl_xor_sync(0xFFFFFFFF, bi, m);
            if (ov > bv || (ov == bv && oi < bi)) { bv = ov; bi = oi; }
        }
        const float* crow = cb + ((size_t)band * NCODE + bi) * NC;
#pragma unroll
        for (int c = lid; c < NC; c += 32)
            out[((size_t)fbb * NC + c) * NT + ft] = crow[c];
    }
}

// ─── launch ───────────────────────────────────────────────────────────────
extern "C" void kernel_launch(void* const* d_in, const int* in_sizes, int n_in,
                              void* d_out, int out_size) {
    const float* x  = (const float*)d_in[0];
    const float* cb = (const float*)d_in[1];
    float* out = (float*)d_out;

    dim3 tiles(TP / TT, BB);  // (12, 80)
    k_split_x<<<tiles, 256>>>(x);
    k_split_cb<<<(NBAND * NCODE + 7) / 8, 256>>>(cb);

    cudaFuncSetAttribute(k_vq_mma, cudaFuncAttributeMaxDynamicSharedMemorySize, SM_TOT);
    k_vq_mma<<<tiles, 256, SM_TOT>>>(cb, out);

    k_fixup<<<FIX_BLOCKS, 256>>>(x, cb, out);
}